// round 15
// baseline (speedup 1.0000x reference)
#include <cuda_runtime.h>
#include <cuda_bf16.h>
#include <cuda_fp16.h>
#include <float.h>
#include <stdint.h>

#define N_NODES 50000
#define N_EDGES 800000
#define F_IN 128
#define H 256
#define KC 32
#define GEMM_TM 128
#define GEMM_NCTA 296

// ---------------- device scratch (no allocs allowed) ----------------
__device__ __half g_Xh [(size_t)N_NODES * F_IN], g_Xl [(size_t)N_NODES * F_IN];
__device__ __half g_AGGh[(size_t)N_NODES * H],   g_AGGl[(size_t)N_NODES * H];
__device__ __half g_H1h[(size_t)N_NODES * H],    g_H1l[(size_t)N_NODES * H];
__device__ __half g_H2h[(size_t)N_NODES * H],    g_H2l[(size_t)N_NODES * H];
__device__ int   g_deg[N_NODES];
__device__ int   g_rowptr[N_NODES + 1];
__device__ int   g_cursor[N_NODES];
__device__ int   g_csrsrc[N_EDGES];
__device__ int   g_part[256];
__device__ int   g_bar;
__device__ __half g_Bt1[256 * 256];
__device__ __half g_Bt2[256 * 512];
__device__ __half g_Bt3[512 * 512];
__device__ float g_b3[512], g_hw[512];

__device__ __forceinline__ uint32_t smem_u32(const void* p) {
    uint32_t a;
    asm("{ .reg .u64 t; cvta.to.shared.u64 t, %1; cvt.u32.u64 %0, t; }" : "=r"(a) : "l"(p));
    return a;
}
__device__ __forceinline__ uint32_t pack2h(float a, float b) {
    __half2 t = __floats2half2_rn(a, b);
    return *reinterpret_cast<uint32_t*>(&t);
}
__device__ __forceinline__ void ldsm_x4(uint32_t* r, uint32_t addr) {
    asm volatile("ldmatrix.sync.aligned.m8n8.x4.shared.b16 {%0,%1,%2,%3}, [%4];"
                 : "=r"(r[0]), "=r"(r[1]), "=r"(r[2]), "=r"(r[3]) : "r"(addr));
}
__device__ __forceinline__ void mma_fp16(float* c, const uint32_t* a, const uint32_t* b) {
    asm volatile(
        "mma.sync.aligned.m16n8k16.row.col.f32.f16.f16.f32 "
        "{%0,%1,%2,%3}, {%4,%5,%6,%7}, {%8,%9}, {%0,%1,%2,%3};"
        : "+f"(c[0]), "+f"(c[1]), "+f"(c[2]), "+f"(c[3])
        : "r"(a[0]), "r"(a[1]), "r"(a[2]), "r"(a[3]), "r"(b[0]), "r"(b[1]));
}
#define CP16(dst, src, pred)                                                  \
    asm volatile("cp.async.cg.shared.global [%0], [%1], 16, %2;"              \
                 :: "r"(dst), "l"(src), "r"((pred) ? 16 : 0) : "memory")

// ---------------- prep ----------------------------------------------------
#define PREP_X0 609265
#define PREP_TOT (PREP_X0 + (N_NODES * F_IN / 4))

__device__ __forceinline__ void pack_one(__half* dh,
                                         const float* Wl, const float* Wr,
                                         int k1, int K, int n_off, int idx) {
    int n = idx / K, k = idx % K;
    float v = (k < k1) ? Wl[(size_t)k * 256 + n] : Wr[(size_t)(k - k1) * 256 + n];
    dh[(size_t)(n_off + n) * K + k] = __float2half_rn(v);
}

__global__ void prep_kernel(const float* x,
                            const float* Wl1, const float* Wr1,
                            const float* Wl2, const float* Wr2,
                            const float* Wla, const float* Wra,
                            const float* Wlm, const float* Wrm,
                            const float* bla, const float* blm,
                            const float* Wa, const float* Wm,
                            const float* ba, const float* bm,
                            float* out) {
    int idx = blockIdx.x * blockDim.x + threadIdx.x;
    if (idx >= PREP_TOT) return;
    if (idx < 50000) {
        g_deg[idx] = 0;
    } else if (idx < 150000) {
        int i = idx - 50000;
        out[i] = (i < N_NODES) ? ba[0] : bm[0];
    } else if (idx < 215536) {
        pack_one(g_Bt1, Wl1, Wr1, 128, 256, 0, idx - 150000);
    } else if (idx < 346608) {
        pack_one(g_Bt2, Wl2, Wr2, 256, 512, 0, idx - 215536);
    } else if (idx < 477680) {
        pack_one(g_Bt3, Wla, Wra, 256, 512, 0, idx - 346608);
    } else if (idx < 608752) {
        pack_one(g_Bt3, Wlm, Wrm, 256, 512, 256, idx - 477680);
    } else if (idx < 609264) {
        int i = idx - 608752;
        if (i < 256) { g_b3[i] = bla[i]; g_hw[i] = Wa[i]; }
        else         { g_b3[i] = blm[i - 256]; g_hw[i] = Wm[i - 256]; }
    } else if (idx == 609264) {
        g_bar = 0;
    } else {
        int j = idx - PREP_X0;
        float4 v = ((const float4*)x)[j];
        __half h0 = __float2half_rn(v.x);
        __half h1 = __float2half_rn(v.y);
        __half h2 = __float2half_rn(v.z);
        __half h3 = __float2half_rn(v.w);
        uint2 hh, ll;
        __half2 p0 = __halves2half2(h0, h1);
        __half2 p1 = __halves2half2(h2, h3);
        hh.x = *reinterpret_cast<uint32_t*>(&p0);
        hh.y = *reinterpret_cast<uint32_t*>(&p1);
        ll.x = pack2h(v.x - __half2float(h0), v.y - __half2float(h1));
        ll.y = pack2h(v.z - __half2float(h2), v.w - __half2float(h3));
        ((uint2*)g_Xh)[j] = hh;
        ((uint2*)g_Xl)[j] = ll;
    }
}

// ---------------- fused CSR build (persistent, fenced grid barrier) -------
#define CSRB 148
#define CSRT 512
#define CHUNK 338

__device__ __forceinline__ void gbar(int phase) {
    __syncthreads();
    __threadfence();
    if (threadIdx.x == 0) {
        atomicAdd(&g_bar, 1);
        while (atomicAdd(&g_bar, 0) < phase * CSRB) { }
    }
    __syncthreads();
}

__global__ void __launch_bounds__(CSRT, 1)
csr_kernel(const void* __restrict__ ei) {
    __shared__ int s[CSRT];
    __shared__ int p[CSRT];
    __shared__ int sh_is64;
    const int tid = threadIdx.x, bid = blockIdx.x;

    if (tid == 0) {
        const int* e = (const int*)ei;
        int ok = 1;
        #pragma unroll 1
        for (int i = 0; i < 64; i++)
            if (e[2 * i + 1] != 0) { ok = 0; break; }
        sh_is64 = ok;
    }
    __syncthreads();
    const int is64 = sh_is64;

    for (int e = bid * CSRT + tid; e < N_EDGES; e += CSRB * CSRT) {
        int d = is64 ? (int)((const long long*)ei)[(size_t)N_EDGES + e]
                     : ((const int*)ei)[N_EDGES + e];
        atomicAdd(&g_deg[d], 1);
    }
    gbar(1);

    const int i0 = bid * CHUNK;
    const int idx = i0 + tid;
    int v = (tid < CHUNK && idx < N_NODES) ? g_deg[idx] : 0;
    s[tid] = v;
    __syncthreads();
    for (int off = 1; off < CSRT; off <<= 1) {
        int t = (tid >= off) ? s[tid - off] : 0;
        __syncthreads();
        s[tid] += t;
        __syncthreads();
    }
    int incl = s[tid];
    if (tid == CSRT - 1) g_part[bid] = s[CSRT - 1];
    gbar(2);

    if (bid == 0) {
        int o = (tid < CSRB) ? g_part[tid] : 0;
        p[tid] = o;
        __syncthreads();
        for (int off = 1; off < CSRT; off <<= 1) {
            int t = (tid >= off) ? p[tid - off] : 0;
            __syncthreads();
            p[tid] += t;
            __syncthreads();
        }
        if (tid < CSRB) g_part[tid] = p[tid] - o;
        if (tid == 0) g_rowptr[N_NODES] = p[CSRB - 1];
    }
    gbar(3);

    int base = g_part[bid];
    if (tid < CHUNK && idx < N_NODES) {
        int ex = base + incl - v;
        g_rowptr[idx] = ex;
        g_cursor[idx] = ex;
    }
    gbar(4);

    for (int e = bid * CSRT + tid; e < N_EDGES; e += CSRB * CSRT) {
        int sN, dN;
        if (is64) {
            sN = (int)((const long long*)ei)[e];
            dN = (int)((const long long*)ei)[(size_t)N_EDGES + e];
        } else {
            sN = ((const int*)ei)[e];
            dN = ((const int*)ei)[N_EDGES + e];
        }
        int pos = atomicAdd(&g_cursor[dN], 1);
        g_csrsrc[pos] = sN;
    }
}

// ---------------- segment max on fp16 hi/lo planes (vectorized) -----------
template <int F>
__global__ void segmax_kernel(const __half* __restrict__ fh,
                              const __half* __restrict__ fl,
                              __half* __restrict__ oh,
                              __half* __restrict__ ol) {
    int node = (blockIdx.x * blockDim.x + threadIdx.x) >> 5;
    int lane = threadIdx.x & 31;
    if (node >= N_NODES) return;
    int beg = g_rowptr[node];
    int end = g_rowptr[node + 1];
    constexpr int NW = F / 64;
    float m[2 * NW];
    #pragma unroll
    for (int i = 0; i < 2 * NW; i++) m[i] = -FLT_MAX;

    auto accum = [&](int src) {
        const uint32_t* ph = (const uint32_t*)(fh + (size_t)src * F);
        const uint32_t* pl = (const uint32_t*)(fl + (size_t)src * F);
        uint32_t hw[NW], lw[NW];
        if (NW == 2) {
            uint2 a = ((const uint2*)ph)[lane];
            uint2 b = ((const uint2*)pl)[lane];
            hw[0] = a.x; hw[1] = a.y; lw[0] = b.x; lw[1] = b.y;
        } else {
            uint4 a = ((const uint4*)ph)[lane];
            uint4 b = ((const uint4*)pl)[lane];
            hw[0] = a.x; hw[1] = a.y; hw[2] = a.z; hw[3] = a.w;
            lw[0] = b.x; lw[1] = b.y; lw[2] = b.z; lw[3] = b.w;
        }
        #pragma unroll
        for (int w = 0; w < NW; w++) {
            __half2 h2 = *reinterpret_cast<__half2*>(&hw[w]);
            __half2 l2 = *reinterpret_cast<__half2*>(&lw[w]);
            m[2 * w]     = fmaxf(m[2 * w],     __half2float(h2.x) + __half2float(l2.x));
            m[2 * w + 1] = fmaxf(m[2 * w + 1], __half2float(h2.y) + __half2float(l2.y));
        }
    };

    int e = beg;
    for (; e + 3 < end; e += 4) {
        accum(g_csrsrc[e]);
        accum(g_csrsrc[e + 1]);
        accum(g_csrsrc[e + 2]);
        accum(g_csrsrc[e + 3]);
    }
    for (; e < end; e++) accum(g_csrsrc[e]);

    if (beg == end) {
        #pragma unroll
        for (int i = 0; i < 2 * NW; i++) m[i] = 0.f;
    }

    uint32_t ohh[NW], oll[NW];
    #pragma unroll
    for (int w = 0; w < NW; w++) {
        float v0 = m[2 * w], v1 = m[2 * w + 1];
        __half h0 = __float2half_rn(v0);
        __half h1 = __float2half_rn(v1);
        __half2 hp = __halves2half2(h0, h1);
        ohh[w] = *reinterpret_cast<uint32_t*>(&hp);
        oll[w] = pack2h(v0 - __half2float(h0), v1 - __half2float(h1));
    }
    uint32_t* poh = (uint32_t*)(oh + (size_t)node * F);
    uint32_t* pol = (uint32_t*)(ol + (size_t)node * F);
    if (NW == 2) {
        ((uint2*)poh)[lane] = make_uint2(ohh[0], ohh[1]);
        ((uint2*)pol)[lane] = make_uint2(oll[0], oll[1]);
    } else {
        ((uint4*)poh)[lane] = make_uint4(ohh[0], ohh[1], ohh[2], ohh[3]);
        ((uint4*)pol)[lane] = make_uint4(oll[0], oll[1], oll[2], oll[3]);
    }
}

// ---------------- persistent mma.sync 2-term fp16 GEMM --------------------
// Tiles 128x128 strided over GEMM_NCTA persistent CTAs (no tail waves).
#define ROWB 80
#define MAT_SZ (128 * ROWB)
#define OFF_AH 0
#define OFF_AL MAT_SZ
#define OFF_B  (2 * MAT_SZ)
#define STAGE_SZ (3 * MAT_SZ)
#define NSTAGE 3
#define GEMM_SMEM (NSTAGE * STAGE_SZ)   // 92160

__global__ void __launch_bounds__(256)
mma_gemm(const __half* __restrict__ a1h, const __half* __restrict__ a1l,
         const __half* __restrict__ a2h, const __half* __restrict__ a2l,
         int k1, int k2, int ntx, int nty,
         const __half* __restrict__ Bt,
         const float* __restrict__ bias, const float* __restrict__ headw,
         __half* __restrict__ Ch, __half* __restrict__ Cl,
         float* __restrict__ outf, int mode) {
    extern __shared__ char smem[];
    const uint32_t sb = smem_u32(smem);
    const int tid = threadIdx.x;
    const int lane = tid & 31, wid = tid >> 5;
    const int warp_m = (wid & 3) * 32;
    const int warp_n = (wid >> 2) * 64;
    const int K = k1 + k2;
    const int NCH = K / KC;
    const int ach = k1 / KC;
    const int ntiles = ntx * nty;

    const int a_row_l = (lane & 7) + ((lane >> 3) & 1) * 8;
    const int a_csel  = lane >> 4;
    const int b_row_l = (lane & 7) + ((lane >> 3) & 2) * 4;
    const int b_csel  = (lane >> 3) & 1;

    const int ar = tid >> 1;
    const int ah2 = tid & 1;
    const int t4r = lane >> 2;
    const int t4c = (lane & 3) * 2;

    for (int tile = blockIdx.x; tile < ntiles; tile += gridDim.x) {
        const int tx = tile % ntx;
        const int ty = tile / ntx;
        const int row0 = tx * GEMM_TM;
        const int nb = ty * 128;
        const int myrow = row0 + ar;
        const bool rok = myrow < N_NODES;

        float acc[2][8][4];
        #pragma unroll
        for (int mi = 0; mi < 2; mi++)
            #pragma unroll
            for (int ni = 0; ni < 8; ni++)
                #pragma unroll
                for (int j = 0; j < 4; j++) acc[mi][ni][j] = 0.f;

        auto issue = [&](int c) {
            const uint32_t stg = sb + (c % NSTAGE) * STAGE_SZ;
            const __half *ph, *pl;
            int stride, kloc;
            if (c < ach) { ph = a1h; pl = a1l; stride = k1; kloc = c * KC; }
            else         { ph = a2h; pl = a2l; stride = k2; kloc = (c - ach) * KC; }
            const char* gah = (const char*)(ph + (size_t)myrow * stride + kloc) + ah2 * 32;
            const char* gal = (const char*)(pl + (size_t)myrow * stride + kloc) + ah2 * 32;
            uint32_t da = stg + ar * ROWB + ah2 * 32;
            CP16(da + OFF_AH,      gah,      rok);
            CP16(da + OFF_AH + 16, gah + 16, rok);
            CP16(da + OFF_AL,      gal,      rok);
            CP16(da + OFF_AL + 16, gal + 16, rok);
            const char* gb = (const char*)(Bt + (size_t)(nb + ar) * K + c * KC) + ah2 * 32;
            CP16(da + OFF_B,      gb,      true);
            CP16(da + OFF_B + 16, gb + 16, true);
            asm volatile("cp.async.commit_group;" ::: "memory");
        };

        issue(0);
        issue(1);
        for (int ch = 0; ch < NCH; ++ch) {
            if (ch + 1 < NCH)
                asm volatile("cp.async.wait_group 1;" ::: "memory");
            else
                asm volatile("cp.async.wait_group 0;" ::: "memory");
            __syncthreads();

            if (ch + 2 < NCH) issue(ch + 2);

            const uint32_t stg = sb + (ch % NSTAGE) * STAGE_SZ;
            #pragma unroll
            for (int kb = 0; kb < 2; kb++) {
                uint32_t Ah[2][4], Al[2][4];
                #pragma unroll
                for (int mi = 0; mi < 2; mi++) {
                    uint32_t addr = stg + (warp_m + mi * 16 + a_row_l) * ROWB +
                                    (kb * 2 + a_csel) * 16;
                    ldsm_x4(Ah[mi], addr + OFF_AH);
                    ldsm_x4(Al[mi], addr + OFF_AL);
                }
                uint32_t Bf[4][4];
                #pragma unroll
                for (int nt = 0; nt < 4; nt++) {
                    uint32_t addr = stg + (warp_n + nt * 16 + b_row_l) * ROWB +
                                    (kb * 2 + b_csel) * 16;
                    ldsm_x4(Bf[nt], addr + OFF_B);
                }
                #pragma unroll
                for (int mi = 0; mi < 2; mi++)
                    #pragma unroll
                    for (int ni = 0; ni < 8; ni++) {
                        const uint32_t* bp = &Bf[ni >> 1][(ni & 1) * 2];
                        mma_fp16(acc[mi][ni], Ah[mi], bp);
                        mma_fp16(acc[mi][ni], Al[mi], bp);
                    }
            }
        }

        // ---- epilogue ----
        if (mode == 0) {
            #pragma unroll
            for (int mi = 0; mi < 2; mi++) {
                #pragma unroll
                for (int half = 0; half < 2; half++) {
                    int row = row0 + warp_m + mi * 16 + half * 8 + t4r;
                    if (row >= N_NODES) continue;
                    #pragma unroll
                    for (int ni = 0; ni < 8; ni++) {
                        int col = nb + warp_n + ni * 8 + t4c;
                        float v0 = fmaxf(acc[mi][ni][half * 2 + 0] + bias[col], 0.f);
                        float v1 = fmaxf(acc[mi][ni][half * 2 + 1] + bias[col + 1], 0.f);
                        __half h0 = __float2half_rn(v0);
                        __half h1 = __float2half_rn(v1);
                        __half2 hp = __halves2half2(h0, h1);
                        size_t off = (size_t)row * 256 + col;
                        *(uint32_t*)(Ch + off) = *reinterpret_cast<uint32_t*>(&hp);
                        *(uint32_t*)(Cl + off) = pack2h(v0 - __half2float(h0),
                                                        v1 - __half2float(h1));
                    }
                }
            }
        } else {
            const int branch = nb >> 8;
            #pragma unroll
            for (int mi = 0; mi < 2; mi++) {
                float s[2] = {0.f, 0.f};
                #pragma unroll
                for (int half = 0; half < 2; half++) {
                    #pragma unroll
                    for (int ni = 0; ni < 8; ni++) {
                        int col = nb + warp_n + ni * 8 + t4c;
                        float v0 = fmaxf(acc[mi][ni][half * 2 + 0] + bias[col], 0.f);
                        float v1 = fmaxf(acc[mi][ni][half * 2 + 1] + bias[col + 1], 0.f);
                        s[half] += v0 * headw[col] + v1 * headw[col + 1];
                    }
                }
                #pragma unroll
                for (int half = 0; half < 2; half++) {
                    float v = s[half];
                    v += __shfl_xor_sync(0xffffffffu, v, 1);
                    v += __shfl_xor_sync(0xffffffffu, v, 2);
                    int row = row0 + warp_m + mi * 16 + half * 8 + t4r;
                    if ((lane & 3) == 0 && row < N_NODES)
                        atomicAdd(&outf[(size_t)branch * N_NODES + row], v);
                }
            }
        }
        __syncthreads();   // smem safe for next tile's cp.async
    }
}

// ---------------- launch ----------------
extern "C" void kernel_launch(void* const* d_in, const int* in_sizes, int n_in,
                              void* d_out, int out_size) {
    const float* x   = (const float*)d_in[0];
    const void*  ei  = d_in[1];
    const float* Wl1 = (const float*)d_in[2];
    const float* bl1 = (const float*)d_in[3];
    const float* Wr1 = (const float*)d_in[4];
    const float* Wl2 = (const float*)d_in[5];
    const float* bl2 = (const float*)d_in[6];
    const float* Wr2 = (const float*)d_in[7];
    const float* Wla = (const float*)d_in[8];
    const float* bla = (const float*)d_in[9];
    const float* Wra = (const float*)d_in[10];
    const float* Wa  = (const float*)d_in[11];
    const float* ba  = (const float*)d_in[12];
    const float* Wlm = (const float*)d_in[13];
    const float* blm = (const float*)d_in[14];
    const float* Wrm = (const float*)d_in[15];
    const float* Wm  = (const float*)d_in[16];
    const float* bm  = (const float*)d_in[17];
    float* out = (float*)d_out;

    __half *Xh, *Xl, *AGGh, *AGGl, *H1h, *H1l, *H2h, *H2l;
    cudaGetSymbolAddress((void**)&Xh,   g_Xh);
    cudaGetSymbolAddress((void**)&Xl,   g_Xl);
    cudaGetSymbolAddress((void**)&AGGh, g_AGGh);
    cudaGetSymbolAddress((void**)&AGGl, g_AGGl);
    cudaGetSymbolAddress((void**)&H1h,  g_H1h);
    cudaGetSymbolAddress((void**)&H1l,  g_H1l);
    cudaGetSymbolAddress((void**)&H2h,  g_H2h);
    cudaGetSymbolAddress((void**)&H2l,  g_H2l);
    __half *Bt1, *Bt2, *Bt3;
    cudaGetSymbolAddress((void**)&Bt1, g_Bt1);
    cudaGetSymbolAddress((void**)&Bt2, g_Bt2);
    cudaGetSymbolAddress((void**)&Bt3, g_Bt3);
    float *b3, *hw;
    cudaGetSymbolAddress((void**)&b3, g_b3);
    cudaGetSymbolAddress((void**)&hw, g_hw);

    cudaFuncSetAttribute(mma_gemm, cudaFuncAttributeMaxDynamicSharedMemorySize, GEMM_SMEM);

    const int TB = 256;
    const int gemm_gx = (N_NODES + GEMM_TM - 1) / GEMM_TM;   // 391
    const int warp_blocks = (N_NODES * 32 + TB - 1) / TB;

    // 1: all elementwise prep (zero deg, packs, x split, out init, bar reset)
    prep_kernel<<<(PREP_TOT + TB - 1) / TB, TB>>>(x, Wl1, Wr1, Wl2, Wr2, Wla, Wra,
                                                  Wlm, Wrm, bla, blm, Wa, Wm,
                                                  ba, bm, out);
    // 2: fused CSR build
    csr_kernel<<<CSRB, CSRT>>>(ei);

    // layer 1
    segmax_kernel<F_IN><<<warp_blocks, TB>>>(Xh, Xl, AGGh, AGGl);
    mma_gemm<<<GEMM_NCTA, 256, GEMM_SMEM>>>(AGGh, AGGl, Xh, Xl, 128, 128,
                                            gemm_gx, 2, Bt1, bl1, nullptr,
                                            H1h, H1l, nullptr, 0);
    // layer 2
    segmax_kernel<H><<<warp_blocks, TB>>>(H1h, H1l, AGGh, AGGl);
    mma_gemm<<<GEMM_NCTA, 256, GEMM_SMEM>>>(AGGh, AGGl, H1h, H1l, 256, 256,
                                            gemm_gx, 2, Bt2, bl2, nullptr,
                                            H2h, H2l, nullptr, 0);
    // shared aggregation + fused dual-branch layer 3 with head epilogue
    segmax_kernel<H><<<warp_blocks, TB>>>(H2h, H2l, AGGh, AGGl);
    mma_gemm<<<GEMM_NCTA, 256, GEMM_SMEM>>>(AGGh, AGGl, H2h, H2l, 256, 256,
                                            gemm_gx, 4, Bt3, b3, hw,
                                            nullptr, nullptr, out, 1);
}

// round 16
// speedup vs baseline: 1.0172x; 1.0172x over previous
#include <cuda_runtime.h>
#include <cuda_bf16.h>
#include <cuda_fp16.h>
#include <float.h>
#include <stdint.h>

#define N_NODES 50000
#define N_EDGES 800000
#define F_IN 128
#define H 256
#define KC 32
#define GEMM_TM 128

// ---------------- device scratch (no allocs allowed) ----------------
__device__ __half g_Xh [(size_t)N_NODES * F_IN], g_Xl [(size_t)N_NODES * F_IN];
__device__ uint32_t g_Xk[(size_t)N_NODES * F_IN];
__device__ __half g_AGGh[(size_t)N_NODES * H],   g_AGGl[(size_t)N_NODES * H];
__device__ __half g_H1h[(size_t)N_NODES * H],    g_H1l[(size_t)N_NODES * H];
__device__ uint32_t g_H1k[(size_t)N_NODES * H];
__device__ __half g_H2h[(size_t)N_NODES * H],    g_H2l[(size_t)N_NODES * H];
__device__ uint32_t g_H2k[(size_t)N_NODES * H];
__device__ int   g_deg[N_NODES];
__device__ int   g_rowptr[N_NODES + 1];
__device__ int   g_cursor[N_NODES];
__device__ int   g_csrsrc[N_EDGES];
__device__ int   g_part[256];
__device__ int   g_bar;
__device__ __half g_Bt1[256 * 256];
__device__ __half g_Bt2[256 * 512];
__device__ __half g_Bt3[512 * 512];
__device__ float g_b3[512], g_hw[512];

__device__ __forceinline__ uint32_t smem_u32(const void* p) {
    uint32_t a;
    asm("{ .reg .u64 t; cvta.to.shared.u64 t, %1; cvt.u32.u64 %0, t; }" : "=r"(a) : "l"(p));
    return a;
}
__device__ __forceinline__ uint32_t pack2h(float a, float b) {
    __half2 t = __floats2half2_rn(a, b);
    return *reinterpret_cast<uint32_t*>(&t);
}
// monotone fp32 -> u32 key (order-preserving), and inverse
__device__ __forceinline__ uint32_t fkey(float v) {
    uint32_t b = __float_as_uint(v);
    return b ^ (uint32_t)(((int32_t)b >> 31) | 0x80000000);
}
__device__ __forceinline__ float funkey(uint32_t k) {
    uint32_t mask = (~(uint32_t)((int32_t)k >> 31)) | 0x80000000u;
    return __uint_as_float(k ^ mask);
}
__device__ __forceinline__ void ldsm_x4(uint32_t* r, uint32_t addr) {
    asm volatile("ldmatrix.sync.aligned.m8n8.x4.shared.b16 {%0,%1,%2,%3}, [%4];"
                 : "=r"(r[0]), "=r"(r[1]), "=r"(r[2]), "=r"(r[3]) : "r"(addr));
}
__device__ __forceinline__ void mma_fp16(float* c, const uint32_t* a, const uint32_t* b) {
    asm volatile(
        "mma.sync.aligned.m16n8k16.row.col.f32.f16.f16.f32 "
        "{%0,%1,%2,%3}, {%4,%5,%6,%7}, {%8,%9}, {%0,%1,%2,%3};"
        : "+f"(c[0]), "+f"(c[1]), "+f"(c[2]), "+f"(c[3])
        : "r"(a[0]), "r"(a[1]), "r"(a[2]), "r"(a[3]), "r"(b[0]), "r"(b[1]));
}
#define CP16(dst, src, pred)                                                  \
    asm volatile("cp.async.cg.shared.global [%0], [%1], 16, %2;"              \
                 :: "r"(dst), "l"(src), "r"((pred) ? 16 : 0) : "memory")

// ---------------- prep ----------------------------------------------------
#define PREP_X0 609265
#define PREP_TOT (PREP_X0 + (N_NODES * F_IN / 4))

__device__ __forceinline__ void pack_one(__half* dh,
                                         const float* Wl, const float* Wr,
                                         int k1, int K, int n_off, int idx) {
    int n = idx / K, k = idx % K;
    float v = (k < k1) ? Wl[(size_t)k * 256 + n] : Wr[(size_t)(k - k1) * 256 + n];
    dh[(size_t)(n_off + n) * K + k] = __float2half_rn(v);
}

__global__ void prep_kernel(const float* x,
                            const float* Wl1, const float* Wr1,
                            const float* Wl2, const float* Wr2,
                            const float* Wla, const float* Wra,
                            const float* Wlm, const float* Wrm,
                            const float* bla, const float* blm,
                            const float* Wa, const float* Wm,
                            const float* ba, const float* bm,
                            float* out) {
    int idx = blockIdx.x * blockDim.x + threadIdx.x;
    if (idx >= PREP_TOT) return;
    if (idx < 50000) {
        g_deg[idx] = 0;
    } else if (idx < 150000) {
        int i = idx - 50000;
        out[i] = (i < N_NODES) ? ba[0] : bm[0];
    } else if (idx < 215536) {
        pack_one(g_Bt1, Wl1, Wr1, 128, 256, 0, idx - 150000);
    } else if (idx < 346608) {
        pack_one(g_Bt2, Wl2, Wr2, 256, 512, 0, idx - 215536);
    } else if (idx < 477680) {
        pack_one(g_Bt3, Wla, Wra, 256, 512, 0, idx - 346608);
    } else if (idx < 608752) {
        pack_one(g_Bt3, Wlm, Wrm, 256, 512, 256, idx - 477680);
    } else if (idx < 609264) {
        int i = idx - 608752;
        if (i < 256) { g_b3[i] = bla[i]; g_hw[i] = Wa[i]; }
        else         { g_b3[i] = blm[i - 256]; g_hw[i] = Wm[i - 256]; }
    } else if (idx == 609264) {
        g_bar = 0;
    } else {
        int j = idx - PREP_X0;
        float4 v = ((const float4*)x)[j];
        __half h0 = __float2half_rn(v.x);
        __half h1 = __float2half_rn(v.y);
        __half h2 = __float2half_rn(v.z);
        __half h3 = __float2half_rn(v.w);
        uint2 hh, ll;
        __half2 p0 = __halves2half2(h0, h1);
        __half2 p1 = __halves2half2(h2, h3);
        hh.x = *reinterpret_cast<uint32_t*>(&p0);
        hh.y = *reinterpret_cast<uint32_t*>(&p1);
        ll.x = pack2h(v.x - __half2float(h0), v.y - __half2float(h1));
        ll.y = pack2h(v.z - __half2float(h2), v.w - __half2float(h3));
        ((uint2*)g_Xh)[j] = hh;
        ((uint2*)g_Xl)[j] = ll;
        ((uint4*)g_Xk)[j] = make_uint4(fkey(v.x), fkey(v.y), fkey(v.z), fkey(v.w));
    }
}

// ---------------- fused CSR build (persistent, fenced grid barrier) -------
#define CSRB 148
#define CSRT 512
#define CHUNK 338

__device__ __forceinline__ void gbar(int phase) {
    __syncthreads();
    __threadfence();
    if (threadIdx.x == 0) {
        atomicAdd(&g_bar, 1);
        while (atomicAdd(&g_bar, 0) < phase * CSRB) { }
    }
    __syncthreads();
}

__global__ void __launch_bounds__(CSRT, 1)
csr_kernel(const void* __restrict__ ei) {
    __shared__ int s[CSRT];
    __shared__ int p[CSRT];
    __shared__ int sh_is64;
    const int tid = threadIdx.x, bid = blockIdx.x;

    if (tid == 0) {
        const int* e = (const int*)ei;
        int ok = 1;
        #pragma unroll 1
        for (int i = 0; i < 64; i++)
            if (e[2 * i + 1] != 0) { ok = 0; break; }
        sh_is64 = ok;
    }
    __syncthreads();
    const int is64 = sh_is64;

    for (int e = bid * CSRT + tid; e < N_EDGES; e += CSRB * CSRT) {
        int d = is64 ? (int)((const long long*)ei)[(size_t)N_EDGES + e]
                     : ((const int*)ei)[N_EDGES + e];
        atomicAdd(&g_deg[d], 1);
    }
    gbar(1);

    const int i0 = bid * CHUNK;
    const int idx = i0 + tid;
    int v = (tid < CHUNK && idx < N_NODES) ? g_deg[idx] : 0;
    s[tid] = v;
    __syncthreads();
    for (int off = 1; off < CSRT; off <<= 1) {
        int t = (tid >= off) ? s[tid - off] : 0;
        __syncthreads();
        s[tid] += t;
        __syncthreads();
    }
    int incl = s[tid];
    if (tid == CSRT - 1) g_part[bid] = s[CSRT - 1];
    gbar(2);

    if (bid == 0) {
        int o = (tid < CSRB) ? g_part[tid] : 0;
        p[tid] = o;
        __syncthreads();
        for (int off = 1; off < CSRT; off <<= 1) {
            int t = (tid >= off) ? p[tid - off] : 0;
            __syncthreads();
            p[tid] += t;
            __syncthreads();
        }
        if (tid < CSRB) g_part[tid] = p[tid] - o;
        if (tid == 0) g_rowptr[N_NODES] = p[CSRB - 1];
    }
    gbar(3);

    int base = g_part[bid];
    if (tid < CHUNK && idx < N_NODES) {
        int ex = base + incl - v;
        g_rowptr[idx] = ex;
        g_cursor[idx] = ex;
    }
    gbar(4);

    for (int e = bid * CSRT + tid; e < N_EDGES; e += CSRB * CSRT) {
        int sN, dN;
        if (is64) {
            sN = (int)((const long long*)ei)[e];
            dN = (int)((const long long*)ei)[(size_t)N_EDGES + e];
        } else {
            sN = ((const int*)ei)[e];
            dN = ((const int*)ei)[N_EDGES + e];
        }
        int pos = atomicAdd(&g_cursor[dN], 1);
        g_csrsrc[pos] = sN;
    }
}

// ---------------- segment max on fp32-key arrays (1 umax per element) -----
// Decodes winning keys to fp16 hi/lo planes for the GEMM.
template <int F>
__global__ void segmax_kernel(const uint32_t* __restrict__ keys,
                              __half* __restrict__ oh,
                              __half* __restrict__ ol) {
    int node = (blockIdx.x * blockDim.x + threadIdx.x) >> 5;
    int lane = threadIdx.x & 31;
    if (node >= N_NODES) return;
    int beg = g_rowptr[node];
    int end = g_rowptr[node + 1];
    constexpr int NK = F / 32;       // key words per lane (4 or 8)
    uint32_t mk[NK];
    #pragma unroll
    for (int i = 0; i < NK; i++) mk[i] = 0u;   // below any real value's key

    auto accum = [&](int src) {
        const uint4* pk = (const uint4*)(keys + (size_t)src * F);
        if (NK == 4) {
            uint4 a = pk[lane];
            mk[0] = max(mk[0], a.x); mk[1] = max(mk[1], a.y);
            mk[2] = max(mk[2], a.z); mk[3] = max(mk[3], a.w);
        } else {
            uint4 a = pk[lane * 2];
            uint4 b = pk[lane * 2 + 1];
            mk[0] = max(mk[0], a.x); mk[1] = max(mk[1], a.y);
            mk[2] = max(mk[2], a.z); mk[3] = max(mk[3], a.w);
            mk[4] = max(mk[4], b.x); mk[5] = max(mk[5], b.y);
            mk[6] = max(mk[6], b.z); mk[7] = max(mk[7], b.w);
        }
    };

    int e = beg;
    for (; e + 3 < end; e += 4) {
        accum(g_csrsrc[e]);
        accum(g_csrsrc[e + 1]);
        accum(g_csrsrc[e + 2]);
        accum(g_csrsrc[e + 3]);
    }
    for (; e < end; e++) accum(g_csrsrc[e]);

    // decode -> fp16 hi/lo planes
    float fv[NK];
    #pragma unroll
    for (int i = 0; i < NK; i++) fv[i] = funkey(mk[i]);
    if (beg == end) {
        #pragma unroll
        for (int i = 0; i < NK; i++) fv[i] = 0.f;
    }

    uint32_t ph[NK / 2], pl[NK / 2];
    #pragma unroll
    for (int w = 0; w < NK / 2; w++) {
        float v0 = fv[2 * w], v1 = fv[2 * w + 1];
        __half h0 = __float2half_rn(v0);
        __half h1 = __float2half_rn(v1);
        __half2 hp = __halves2half2(h0, h1);
        ph[w] = *reinterpret_cast<uint32_t*>(&hp);
        pl[w] = pack2h(v0 - __half2float(h0), v1 - __half2float(h1));
    }
    uint32_t* poh = (uint32_t*)(oh + (size_t)node * F);
    uint32_t* pol = (uint32_t*)(ol + (size_t)node * F);
    if (NK == 4) {
        ((uint2*)poh)[lane] = make_uint2(ph[0], ph[1]);
        ((uint2*)pol)[lane] = make_uint2(pl[0], pl[1]);
    } else {
        ((uint4*)poh)[lane] = make_uint4(ph[0], ph[1], ph[2], ph[3]);
        ((uint4*)pol)[lane] = make_uint4(pl[0], pl[1], pl[2], pl[3]);
    }
}

// ---------------- mma.sync 2-term fp16 GEMM, 3-stage cp.async ring --------
#define ROWB 80
#define MAT_SZ (128 * ROWB)
#define OFF_AH 0
#define OFF_AL MAT_SZ
#define OFF_B  (2 * MAT_SZ)
#define STAGE_SZ (3 * MAT_SZ)
#define NSTAGE 3
#define GEMM_SMEM (NSTAGE * STAGE_SZ)   // 92160

__global__ void __launch_bounds__(256)
mma_gemm(const __half* __restrict__ a1h, const __half* __restrict__ a1l,
         const __half* __restrict__ a2h, const __half* __restrict__ a2l,
         int k1, int k2,
         const __half* __restrict__ Bt,
         const float* __restrict__ bias, const float* __restrict__ headw,
         __half* __restrict__ Ch, __half* __restrict__ Cl,
         uint32_t* __restrict__ Ck,
         float* __restrict__ outf, int mode) {
    extern __shared__ char smem[];
    const uint32_t sb = smem_u32(smem);
    const int tid = threadIdx.x;
    const int lane = tid & 31, wid = tid >> 5;
    const int warp_m = (wid & 3) * 32;
    const int warp_n = (wid >> 2) * 64;
    const int row0 = blockIdx.x * GEMM_TM;
    const int nb = blockIdx.y * 128;
    const int K = k1 + k2;
    const int NCH = K / KC;
    const int ach = k1 / KC;

    const int a_row_l = (lane & 7) + ((lane >> 3) & 1) * 8;
    const int a_csel  = lane >> 4;
    const int b_row_l = (lane & 7) + ((lane >> 3) & 2) * 4;
    const int b_csel  = (lane >> 3) & 1;

    const int ar = tid >> 1;
    const int ah2 = tid & 1;
    const int myrow = row0 + ar;
    const bool rok = myrow < N_NODES;

    float acc[2][8][4];
    #pragma unroll
    for (int mi = 0; mi < 2; mi++)
        #pragma unroll
        for (int ni = 0; ni < 8; ni++)
            #pragma unroll
            for (int j = 0; j < 4; j++) acc[mi][ni][j] = 0.f;

    auto issue = [&](int c) {
        const uint32_t stg = sb + (c % NSTAGE) * STAGE_SZ;
        const __half *ph, *pl;
        int stride, kloc;
        if (c < ach) { ph = a1h; pl = a1l; stride = k1; kloc = c * KC; }
        else         { ph = a2h; pl = a2l; stride = k2; kloc = (c - ach) * KC; }
        const char* gah = (const char*)(ph + (size_t)myrow * stride + kloc) + ah2 * 32;
        const char* gal = (const char*)(pl + (size_t)myrow * stride + kloc) + ah2 * 32;
        uint32_t da = stg + ar * ROWB + ah2 * 32;
        CP16(da + OFF_AH,      gah,      rok);
        CP16(da + OFF_AH + 16, gah + 16, rok);
        CP16(da + OFF_AL,      gal,      rok);
        CP16(da + OFF_AL + 16, gal + 16, rok);
        const char* gb = (const char*)(Bt + (size_t)(nb + ar) * K + c * KC) + ah2 * 32;
        CP16(da + OFF_B,      gb,      true);
        CP16(da + OFF_B + 16, gb + 16, true);
        asm volatile("cp.async.commit_group;" ::: "memory");
    };

    issue(0);
    issue(1);
    for (int ch = 0; ch < NCH; ++ch) {
        if (ch + 1 < NCH)
            asm volatile("cp.async.wait_group 1;" ::: "memory");
        else
            asm volatile("cp.async.wait_group 0;" ::: "memory");
        __syncthreads();

        if (ch + 2 < NCH) issue(ch + 2);

        const uint32_t stg = sb + (ch % NSTAGE) * STAGE_SZ;
        #pragma unroll
        for (int kb = 0; kb < 2; kb++) {
            uint32_t Ah[2][4], Al[2][4];
            #pragma unroll
            for (int mi = 0; mi < 2; mi++) {
                uint32_t addr = stg + (warp_m + mi * 16 + a_row_l) * ROWB +
                                (kb * 2 + a_csel) * 16;
                ldsm_x4(Ah[mi], addr + OFF_AH);
                ldsm_x4(Al[mi], addr + OFF_AL);
            }
            uint32_t Bf[4][4];
            #pragma unroll
            for (int nt = 0; nt < 4; nt++) {
                uint32_t addr = stg + (warp_n + nt * 16 + b_row_l) * ROWB +
                                (kb * 2 + b_csel) * 16;
                ldsm_x4(Bf[nt], addr + OFF_B);
            }
            #pragma unroll
            for (int mi = 0; mi < 2; mi++)
                #pragma unroll
                for (int ni = 0; ni < 8; ni++) {
                    const uint32_t* bp = &Bf[ni >> 1][(ni & 1) * 2];
                    mma_fp16(acc[mi][ni], Ah[mi], bp);
                    mma_fp16(acc[mi][ni], Al[mi], bp);
                }
        }
    }

    // ---- epilogue ----
    const int t4r = lane >> 2;
    const int t4c = (lane & 3) * 2;
    if (mode == 0) {
        #pragma unroll
        for (int mi = 0; mi < 2; mi++) {
            #pragma unroll
            for (int half = 0; half < 2; half++) {
                int row = row0 + warp_m + mi * 16 + half * 8 + t4r;
                if (row >= N_NODES) continue;
                #pragma unroll
                for (int ni = 0; ni < 8; ni++) {
                    int col = nb + warp_n + ni * 8 + t4c;
                    float v0 = fmaxf(acc[mi][ni][half * 2 + 0] + bias[col], 0.f);
                    float v1 = fmaxf(acc[mi][ni][half * 2 + 1] + bias[col + 1], 0.f);
                    __half h0 = __float2half_rn(v0);
                    __half h1 = __float2half_rn(v1);
                    __half2 hp = __halves2half2(h0, h1);
                    size_t off = (size_t)row * 256 + col;
                    *(uint32_t*)(Ch + off) = *reinterpret_cast<uint32_t*>(&hp);
                    *(uint32_t*)(Cl + off) = pack2h(v0 - __half2float(h0),
                                                    v1 - __half2float(h1));
                    *(uint2*)(Ck + off) = make_uint2(fkey(v0), fkey(v1));
                }
            }
        }
    } else {
        const int branch = nb >> 8;
        #pragma unroll
        for (int mi = 0; mi < 2; mi++) {
            float s[2] = {0.f, 0.f};
            #pragma unroll
            for (int half = 0; half < 2; half++) {
                #pragma unroll
                for (int ni = 0; ni < 8; ni++) {
                    int col = nb + warp_n + ni * 8 + t4c;
                    float v0 = fmaxf(acc[mi][ni][half * 2 + 0] + bias[col], 0.f);
                    float v1 = fmaxf(acc[mi][ni][half * 2 + 1] + bias[col + 1], 0.f);
                    s[half] += v0 * headw[col] + v1 * headw[col + 1];
                }
            }
            #pragma unroll
            for (int half = 0; half < 2; half++) {
                float v = s[half];
                v += __shfl_xor_sync(0xffffffffu, v, 1);
                v += __shfl_xor_sync(0xffffffffu, v, 2);
                int row = row0 + warp_m + mi * 16 + half * 8 + t4r;
                if ((lane & 3) == 0 && row < N_NODES)
                    atomicAdd(&outf[(size_t)branch * N_NODES + row], v);
            }
        }
    }
}

// ---------------- launch ----------------
extern "C" void kernel_launch(void* const* d_in, const int* in_sizes, int n_in,
                              void* d_out, int out_size) {
    const float* x   = (const float*)d_in[0];
    const void*  ei  = d_in[1];
    const float* Wl1 = (const float*)d_in[2];
    const float* bl1 = (const float*)d_in[3];
    const float* Wr1 = (const float*)d_in[4];
    const float* Wl2 = (const float*)d_in[5];
    const float* bl2 = (const float*)d_in[6];
    const float* Wr2 = (const float*)d_in[7];
    const float* Wla = (const float*)d_in[8];
    const float* bla = (const float*)d_in[9];
    const float* Wra = (const float*)d_in[10];
    const float* Wa  = (const float*)d_in[11];
    const float* ba  = (const float*)d_in[12];
    const float* Wlm = (const float*)d_in[13];
    const float* blm = (const float*)d_in[14];
    const float* Wrm = (const float*)d_in[15];
    const float* Wm  = (const float*)d_in[16];
    const float* bm  = (const float*)d_in[17];
    float* out = (float*)d_out;

    __half *Xh, *Xl, *AGGh, *AGGl, *H1h, *H1l, *H2h, *H2l;
    uint32_t *Xk, *H1k, *H2k;
    cudaGetSymbolAddress((void**)&Xh,   g_Xh);
    cudaGetSymbolAddress((void**)&Xl,   g_Xl);
    cudaGetSymbolAddress((void**)&Xk,   g_Xk);
    cudaGetSymbolAddress((void**)&AGGh, g_AGGh);
    cudaGetSymbolAddress((void**)&AGGl, g_AGGl);
    cudaGetSymbolAddress((void**)&H1h,  g_H1h);
    cudaGetSymbolAddress((void**)&H1l,  g_H1l);
    cudaGetSymbolAddress((void**)&H1k,  g_H1k);
    cudaGetSymbolAddress((void**)&H2h,  g_H2h);
    cudaGetSymbolAddress((void**)&H2l,  g_H2l);
    cudaGetSymbolAddress((void**)&H2k,  g_H2k);
    __half *Bt1, *Bt2, *Bt3;
    cudaGetSymbolAddress((void**)&Bt1, g_Bt1);
    cudaGetSymbolAddress((void**)&Bt2, g_Bt2);
    cudaGetSymbolAddress((void**)&Bt3, g_Bt3);
    float *b3, *hw;
    cudaGetSymbolAddress((void**)&b3, g_b3);
    cudaGetSymbolAddress((void**)&hw, g_hw);

    cudaFuncSetAttribute(mma_gemm, cudaFuncAttributeMaxDynamicSharedMemorySize, GEMM_SMEM);

    const int TB = 256;
    const int gemm_gx = (N_NODES + GEMM_TM - 1) / GEMM_TM;   // 391
    const int warp_blocks = (N_NODES * 32 + TB - 1) / TB;

    // 1: all elementwise prep (zero deg, packs, x split+keys, out init, bar reset)
    prep_kernel<<<(PREP_TOT + TB - 1) / TB, TB>>>(x, Wl1, Wr1, Wl2, Wr2, Wla, Wra,
                                                  Wlm, Wrm, bla, blm, Wa, Wm,
                                                  ba, bm, out);
    // 2: fused CSR build
    csr_kernel<<<CSRB, CSRT>>>(ei);

    // layer 1
    segmax_kernel<F_IN><<<warp_blocks, TB>>>(Xk, AGGh, AGGl);
    mma_gemm<<<dim3(gemm_gx, 2), 256, GEMM_SMEM>>>(AGGh, AGGl, Xh, Xl, 128, 128,
                                                   Bt1, bl1, nullptr,
                                                   H1h, H1l, H1k, nullptr, 0);
    // layer 2
    segmax_kernel<H><<<warp_blocks, TB>>>(H1k, AGGh, AGGl);
    mma_gemm<<<dim3(gemm_gx, 2), 256, GEMM_SMEM>>>(AGGh, AGGl, H1h, H1l, 256, 256,
                                                   Bt2, bl2, nullptr,
                                                   H2h, H2l, H2k, nullptr, 0);
    // shared aggregation + fused dual-branch layer 3 with head epilogue
    segmax_kernel<H><<<warp_blocks, TB>>>(H2k, AGGh, AGGl);
    mma_gemm<<<dim3(gemm_gx, 4), 256, GEMM_SMEM>>>(AGGh, AGGl, H2h, H2l, 256, 256,
                                                   Bt3, b3, hw,
                                                   nullptr, nullptr, nullptr, out, 1);
}